// round 3
// baseline (speedup 1.0000x reference)
#include <cuda_runtime.h>
#include <math.h>

// Problem constants
#define BB   8
#define PP   2048
#define DD   1024
#define EE   16
#define SS   64
#define DKK  128
#define HH   16
#define NTOK (BB*PP)          // 16384
#define TOK  8                // tokens per CTA
#define THREADS 512

__device__ __forceinline__ float sigmoidf_(float v) { return 1.0f / (1.0f + expf(-v)); }

struct __align__(16) Smem {
    float fT[DD][TOK];          // 32 KB : xn, later f = xn*gscale ; [channel][token]
    float V2[EE][TOK][DKK];     // 64 KB : V[e][t][d]
    float h_s[EE][HH][TOK];     // 8 KB
    float Vp_s[TOK][EE][8];     // padded 5->8
    float gscale[TOK][EE];
    float mask_s[TOK][EE];
    float mw_s[TOK][EE];
    float den_s[TOK];
    float fused_s[TOK];
    float we_s[EE];
    float aw_s[EE];
    float pinv_s[EE * 5];
    float lnpart[TOK][2][2];    // [token][half][sum, sumsq]
};

__global__ __launch_bounds__(THREADS, 2)
void cantor_moe_kernel(
    const float* __restrict__ x,
    const float* __restrict__ fingerprints,
    const float* __restrict__ ln_gamma,
    const float* __restrict__ ln_beta,
    const float* __restrict__ w1,
    const float* __restrict__ b1,
    const float* __restrict__ w2,
    const float* __restrict__ b2,
    const float* __restrict__ alpha,
    const float* __restrict__ wv,
    const float* __restrict__ penta,
    const float* __restrict__ betas,
    const float* __restrict__ wout,
    const float* __restrict__ pos_embed,
    const float* __restrict__ temperature,
    float* __restrict__ out)
{
    extern __shared__ unsigned char smem_raw[];
    Smem& sm = *reinterpret_cast<Smem*>(smem_raw);

    const int tid  = threadIdx.x;
    const int warp = tid >> 5;
    const int lane = tid & 31;
    const long g0  = (long)blockIdx.x * TOK;   // first global token of this CTA

    // ---------------- P0: per-expert constants (warp e handles expert e) ----
    {
        const int e = warp;
        // pos_w = sigmoid(mean(pos_embed[e]))
        float4 pv = reinterpret_cast<const float4*>(pos_embed)[e * 32 + lane];
        float psum = pv.x + pv.y + pv.z + pv.w;
        #pragma unroll
        for (int o = 16; o; o >>= 1) psum += __shfl_xor_sync(0xffffffffu, psum, o);
        if (lane == 0) {
            float pos_w = sigmoidf_(psum * (1.0f / 128.0f));
            const int offs[4] = {-2, -1, 1, 2};
            float nv = 0.0f, bs = 0.0f;
            #pragma unroll
            for (int j = 0; j < 4; j++) {
                int nb = e + offs[j];
                if (nb >= 0 && nb < EE) { nv += 1.0f; bs += sigmoidf_(betas[e * 4 + j]); }
            }
            sm.we_s[e] = pos_w * (1.0f + bs / nv);
            sm.aw_s[e] = sigmoidf_(alpha[e]);
        }
        // inverse norms of pentachoron rows (5 per warp)
        #pragma unroll
        for (int k = 0; k < 5; k++) {
            int i = warp * 5 + k;                       // 0..79 : e = i/5, v = i%5
            float4 v = reinterpret_cast<const float4*>(penta + (long)i * DKK)[lane];
            float sq = v.x * v.x + v.y * v.y + v.z * v.z + v.w * v.w;
            #pragma unroll
            for (int o = 16; o; o >>= 1) sq += __shfl_xor_sync(0xffffffffu, sq, o);
            if (lane == 0) sm.pinv_s[i] = rsqrtf(sq);
        }
    }

    // ---------------- P2: LayerNorm (2 warps per token) ---------------------
    {
        const int t    = warp & 7;
        const int half = warp >> 3;
        const long g   = g0 + t;
        const float4* xr = reinterpret_cast<const float4*>(x + g * DD);
        float4 v[4];
        float s = 0.0f, sq = 0.0f;
        #pragma unroll
        for (int i = 0; i < 4; i++) {
            v[i] = xr[half * 128 + i * 32 + lane];
            s  += v[i].x + v[i].y + v[i].z + v[i].w;
            sq += v[i].x * v[i].x + v[i].y * v[i].y + v[i].z * v[i].z + v[i].w * v[i].w;
        }
        #pragma unroll
        for (int o = 16; o; o >>= 1) {
            s  += __shfl_xor_sync(0xffffffffu, s,  o);
            sq += __shfl_xor_sync(0xffffffffu, sq, o);
        }
        if (lane == 0) { sm.lnpart[t][half][0] = s; sm.lnpart[t][half][1] = sq; }
        __syncthreads();   // (A) all warps

        float mean = (sm.lnpart[t][0][0] + sm.lnpart[t][1][0]) * (1.0f / DD);
        float m2   = (sm.lnpart[t][0][1] + sm.lnpart[t][1][1]) * (1.0f / DD);
        float rstd = rsqrtf(m2 - mean * mean + 1e-5f);
        #pragma unroll
        for (int i = 0; i < 4; i++) {
            int c4 = half * 128 + i * 32 + lane;
            float4 gm = reinterpret_cast<const float4*>(ln_gamma)[c4];
            float4 bt = reinterpret_cast<const float4*>(ln_beta)[c4];
            int c = c4 * 4;
            sm.fT[c + 0][t] = (v[i].x - mean) * rstd * gm.x + bt.x;
            sm.fT[c + 1][t] = (v[i].y - mean) * rstd * gm.y + bt.y;
            sm.fT[c + 2][t] = (v[i].z - mean) * rstd * gm.z + bt.z;
            sm.fT[c + 3][t] = (v[i].w - mean) * rstd * gm.w + bt.w;
        }
    }

    // ---------------- P1: masks / mw (needs we_s, written before sync A) ----
    if (tid < TOK * EE) {
        const int t = tid >> 4, e = tid & 15;
        const long g = g0 + t;
        float f = fingerprints[(int)(g & (PP - 1))];
        float fmin = fmaxf(0.0f, e * (1.0f / EE) - 0.03125f);
        float fmax = fminf(1.0f, (e + 1) * (1.0f / EE) + 0.03125f);
        float mval = (f >= fmin && f < fmax) ? 1.0f : 0.0f;
        sm.mask_s[t][e] = mval;
        sm.mw_s[t][e]   = mval * sm.we_s[e];
    }
    __syncthreads();       // (B) fT(xn), mw ready

    if (tid >= 448 && tid < 448 + TOK) {
        const int t = tid - 448;
        float s = 0.0f;
        #pragma unroll
        for (int e = 0; e < EE; e++) s += sm.mw_s[t][e];
        sm.den_s[t] = fmaxf(s, 1e-6f);
    }

    // ---------------- P3: gate hidden layer  (threads 0..255 => (e,j)) ------
    if (tid < EE * HH) {
        const int e = tid >> 4, j = tid & 15;
        float acc[TOK];
        #pragma unroll
        for (int t = 0; t < TOK; t++) acc[t] = 0.0f;
        const float* w1p  = w1 + (long)(e * SS) * HH + j;
        const float* fptr = &sm.fT[e * SS][0];
        #pragma unroll 4
        for (int s = 0; s < SS; s++) {
            float w = w1p[s * HH];
            float4 fa = *reinterpret_cast<const float4*>(fptr + s * TOK);
            float4 fb = *reinterpret_cast<const float4*>(fptr + s * TOK + 4);
            acc[0] = fmaf(fa.x, w, acc[0]); acc[1] = fmaf(fa.y, w, acc[1]);
            acc[2] = fmaf(fa.z, w, acc[2]); acc[3] = fmaf(fa.w, w, acc[3]);
            acc[4] = fmaf(fb.x, w, acc[4]); acc[5] = fmaf(fb.y, w, acc[5]);
            acc[6] = fmaf(fb.z, w, acc[6]); acc[7] = fmaf(fb.w, w, acc[7]);
        }
        float bb1 = b1[e * HH + j];
        #pragma unroll
        for (int t = 0; t < TOK; t++) {
            float hv = acc[t] + bb1;
            hv = 0.5f * hv * (1.0f + erff(hv * 0.70710678118654752f));
            sm.h_s[e][j][t] = hv;
        }
    }
    __syncthreads();       // (C)

    // ---------------- P4: gate output + blend scale --------------------------
    if (tid < TOK * EE) {
        const int t = tid >> 4, e = tid & 15;
        float s = 0.0f;
        #pragma unroll
        for (int j = 0; j < HH; j++) s += sm.h_s[e][j][t] * w2[e * HH + j];
        float gate = sigmoidf_(s + b2[e]);
        float aw = sm.aw_s[e];
        sm.gscale[t][e] = gate * aw + (1.0f - aw);
    }
    __syncthreads();       // (D)

    // ---------------- P5: f = xn * gscale  (in place) ------------------------
    #pragma unroll
    for (int k = 0; k < (DD * TOK) / THREADS; k++) {
        int idx = tid + k * THREADS;       // 0..8191, t fastest
        int c = idx >> 3, t = idx & 7;
        sm.fT[c][t] *= sm.gscale[t][c >> 6];
    }
    __syncthreads();       // (E)

    // ---------------- P6: V[e] = f_e @ wv[e]   (two expert groups of 8) ------
    {
        const int eb = tid >> 6;            // 0..7
        const int tq = (tid >> 5) & 1;      // token quad
        const int l  = tid & 31;            // d-quad index
        #pragma unroll
        for (int eg = 0; eg < 2; eg++) {
            const int e = eb + eg * 8;
            float acc[4][4];
            #pragma unroll
            for (int a = 0; a < 4; a++)
                #pragma unroll
                for (int b = 0; b < 4; b++) acc[a][b] = 0.0f;
            const float4* wvp = reinterpret_cast<const float4*>(wv + (long)e * SS * DKK) + l;
            const float*  fp0 = &sm.fT[e * SS][tq * 4];
            #pragma unroll 4
            for (int s = 0; s < SS; s++) {
                float4 w  = wvp[s * 32];
                float4 f4 = *reinterpret_cast<const float4*>(fp0 + s * TOK);
                float fv[4] = {f4.x, f4.y, f4.z, f4.w};
                float wa[4] = {w.x, w.y, w.z, w.w};
                #pragma unroll
                for (int ti = 0; ti < 4; ti++)
                    #pragma unroll
                    for (int di = 0; di < 4; di++)
                        acc[ti][di] = fmaf(fv[ti], wa[di], acc[ti][di]);
            }
            #pragma unroll
            for (int ti = 0; ti < 4; ti++) {
                float4 o = make_float4(acc[ti][0], acc[ti][1], acc[ti][2], acc[ti][3]);
                *reinterpret_cast<float4*>(&sm.V2[e][tq * 4 + ti][l * 4]) = o;
            }
        }
    }
    __syncthreads();       // (F)

    // ---------------- P7: pentachoron projections ----------------------------
    {
        #pragma unroll
        for (int k = 0; k < 8; k++) {
            const int q = warp * 8 + k;      // 0..127
            const int t = q >> 4, e = q & 15;
            float4 v = *(reinterpret_cast<const float4*>(&sm.V2[e][t][0]) + lane);
            const float4* pp = reinterpret_cast<const float4*>(penta + (long)e * 5 * DKK) + lane;
            #pragma unroll
            for (int vtx = 0; vtx < 5; vtx++) {
                float4 pv = pp[vtx * 32];
                float d = v.x * pv.x + v.y * pv.y + v.z * pv.z + v.w * pv.w;
                #pragma unroll
                for (int o = 16; o; o >>= 1) d += __shfl_xor_sync(0xffffffffu, d, o);
                if (lane == 0) sm.Vp_s[t][e][vtx] = d * sm.pinv_s[e * 5 + vtx];
            }
        }
    }
    __syncthreads();       // (G)

    // ---------------- P8: fused scalar per token ------------------------------
    if (tid < TOK) {
        const int t = tid;
        float s = 0.0f;
        #pragma unroll
        for (int e = 0; e < EE; e++) {
            float mwv = sm.mw_s[t][e];
            #pragma unroll
            for (int v = 0; v < 5; v++) s += sm.Vp_s[t][e][v] * mwv;
        }
        sm.fused_s[t] = s / (5.0f * sm.den_s[t] * fabsf(temperature[0]));
    }
    __syncthreads();       // (H)

    // ---------------- P9: rec = (V*fused) @ wout, mask, residual add ----------
    {
        const int e  = warp;                 // warp == expert
        const int tq = lane >> 4;
        const int sl = lane & 15;            // s quad
        float acc[4][4];
        #pragma unroll
        for (int a = 0; a < 4; a++)
            #pragma unroll
            for (int b = 0; b < 4; b++) acc[a][b] = 0.0f;
        const float4* wop = reinterpret_cast<const float4*>(wout + (long)e * DKK * SS) + sl;
        #pragma unroll 2
        for (int db = 0; db < DKK / 4; db++) {
            float vtf[4][4];
            #pragma unroll
            for (int ti = 0; ti < 4; ti++) {
                float4 vt = *reinterpret_cast<const float4*>(&sm.V2[e][tq * 4 + ti][db * 4]);
                vtf[ti][0] = vt.x; vtf[ti][1] = vt.y; vtf[ti][2] = vt.z; vtf[ti][3] = vt.w;
            }
            #pragma unroll
            for (int i = 0; i < 4; i++) {
                float4 w = wop[(db * 4 + i) * 16];
                float wa[4] = {w.x, w.y, w.z, w.w};
                #pragma unroll
                for (int ti = 0; ti < 4; ti++)
                    #pragma unroll
                    for (int j = 0; j < 4; j++)
                        acc[ti][j] = fmaf(vtf[ti][i], wa[j], acc[ti][j]);
            }
        }
        #pragma unroll
        for (int ti = 0; ti < 4; ti++) {
            const int t = tq * 4 + ti;
            const long g = g0 + t;
            float fs = sm.fused_s[t] * sm.mask_s[t][e];
            const float4 xv = reinterpret_cast<const float4*>(x + g * DD + e * SS)[sl];
            float4 ov;
            ov.x = xv.x + fs * acc[ti][0];
            ov.y = xv.y + fs * acc[ti][1];
            ov.z = xv.z + fs * acc[ti][2];
            ov.w = xv.w + fs * acc[ti][3];
            reinterpret_cast<float4*>(out + g * DD + e * SS)[sl] = ov;
        }
    }
}

extern "C" void kernel_launch(void* const* d_in, const int* in_sizes, int n_in,
                              void* d_out, int out_size)
{
    (void)in_sizes; (void)n_in; (void)out_size;
    const float* x            = (const float*)d_in[0];
    const float* fingerprints = (const float*)d_in[1];
    const float* ln_gamma     = (const float*)d_in[2];
    const float* ln_beta      = (const float*)d_in[3];
    const float* w1           = (const float*)d_in[4];
    const float* b1           = (const float*)d_in[5];
    const float* w2           = (const float*)d_in[6];
    const float* b2           = (const float*)d_in[7];
    const float* alpha        = (const float*)d_in[8];
    const float* wv           = (const float*)d_in[9];
    const float* penta        = (const float*)d_in[10];
    const float* betas        = (const float*)d_in[11];
    const float* wout         = (const float*)d_in[12];
    const float* pos_embed    = (const float*)d_in[13];
    const float* temperature  = (const float*)d_in[14];
    float* out = (float*)d_out;

    cudaFuncSetAttribute(cantor_moe_kernel,
                         cudaFuncAttributeMaxDynamicSharedMemorySize,
                         (int)sizeof(Smem));

    dim3 grid(NTOK / TOK);
    cantor_moe_kernel<<<grid, THREADS, sizeof(Smem)>>>(
        x, fingerprints, ln_gamma, ln_beta, w1, b1, w2, b2, alpha,
        wv, penta, betas, wout, pos_embed, temperature, out);
}

// round 6
// speedup vs baseline: 1.4458x; 1.4458x over previous
#include <cuda_runtime.h>
#include <math.h>

// Problem constants
#define BB   8
#define PP   2048
#define DD   1024
#define EE   16
#define SS   64
#define DKK  128
#define HH   16
#define NTOK (BB*PP)          // 16384
#define TOK  16               // tokens per CTA
#define TOKP 18               // padded token row (bank-conflict relief, keeps 8B align)
#define THREADS 512

typedef unsigned long long ull;

__device__ __forceinline__ float sigmoidf_(float v) { return 1.0f / (1.0f + expf(-v)); }

// packed f32x2 helpers (sm_100+): FFMA2 doubles fp32 FMA throughput per instr
__device__ __forceinline__ ull pk(float lo, float hi) {
    ull r; asm("mov.b64 %0,{%1,%2};" : "=l"(r) : "f"(lo), "f"(hi)); return r;
}
__device__ __forceinline__ void upk(ull v, float& lo, float& hi) {
    asm("mov.b64 {%0,%1},%2;" : "=f"(lo), "=f"(hi) : "l"(v));
}
__device__ __forceinline__ void ffma2(ull& acc, ull a, ull b) {
    asm("fma.rn.f32x2 %0,%1,%2,%0;" : "+l"(acc) : "l"(a), "l"(b));
}
__device__ __forceinline__ ull mul2(ull a, ull b) {
    ull r; asm("mul.rn.f32x2 %0,%1,%2;" : "=l"(r) : "l"(a), "l"(b)); return r;
}

struct __align__(16) Smem {
    float fT[DD][TOKP];         // 73728 B : xn then f, [channel][token] (token pairs 8B-contig)
    float V2[EE][TOK][DKK];     // 131072 B : V[e][t][d]  (first 16KB aliased as h_s pre-P6)
    float dbar[EE][DKK];        // 8192 B  : (1/5) sum_v normalized penta dirs
    float Vdb[TOK][EE];
    float gscale[EE][TOK];      // [e][t] so token pairs are 8B-contiguous
    float mask_s[TOK][EE];
    float mw_s[TOK][EE];
    float den_s[TOK];
    float fused_s[TOK];
    float we_s[EE];
    float aw_s[EE];
};

__global__ __launch_bounds__(THREADS, 1)
void cantor_moe_kernel(
    const float* __restrict__ x,
    const float* __restrict__ fingerprints,
    const float* __restrict__ ln_gamma,
    const float* __restrict__ ln_beta,
    const float* __restrict__ w1,
    const float* __restrict__ b1,
    const float* __restrict__ w2,
    const float* __restrict__ b2,
    const float* __restrict__ alpha,
    const float* __restrict__ wv,
    const float* __restrict__ penta,
    const float* __restrict__ betas,
    const float* __restrict__ wout,
    const float* __restrict__ pos_embed,
    const float* __restrict__ temperature,
    float* __restrict__ out)
{
    extern __shared__ unsigned char smem_raw[];
    Smem& sm = *reinterpret_cast<Smem*>(smem_raw);
    float (*h_s)[HH][TOK] = reinterpret_cast<float(*)[HH][TOK]>(&sm.V2[0][0][0]);

    const int tid  = threadIdx.x;
    const int warp = tid >> 5;           // 0..15
    const int lane = tid & 31;
    const long g0  = (long)blockIdx.x * TOK;

    // ---------------- P0: per-expert constants + dbar (warp e) --------------
    {
        const int e = warp;
        // pos_w = sigmoid(mean(pos_embed[e]))
        float4 pv = reinterpret_cast<const float4*>(pos_embed)[e * 32 + lane];
        float psum = pv.x + pv.y + pv.z + pv.w;
        #pragma unroll
        for (int o = 16; o; o >>= 1) psum += __shfl_xor_sync(0xffffffffu, psum, o);
        if (lane == 0) {
            float pos_w = sigmoidf_(psum * (1.0f / 128.0f));
            const int offs[4] = {-2, -1, 1, 2};
            float nv = 0.0f, bs = 0.0f;
            #pragma unroll
            for (int j = 0; j < 4; j++) {
                int nb = e + offs[j];
                if (nb >= 0 && nb < EE) { nv += 1.0f; bs += sigmoidf_(betas[e * 4 + j]); }
            }
            sm.we_s[e] = pos_w * (1.0f + bs / nv);
            sm.aw_s[e] = sigmoidf_(alpha[e]);
        }
        // dbar[e] = (1/5) sum_v penta[e][v] / ||penta[e][v]||
        float4 db = make_float4(0.f, 0.f, 0.f, 0.f);
        #pragma unroll
        for (int v = 0; v < 5; v++) {
            float4 p4 = reinterpret_cast<const float4*>(penta + (long)(e * 5 + v) * DKK)[lane];
            float sq = p4.x * p4.x + p4.y * p4.y + p4.z * p4.z + p4.w * p4.w;
            #pragma unroll
            for (int o = 16; o; o >>= 1) sq += __shfl_xor_sync(0xffffffffu, sq, o);
            float piv = rsqrtf(sq) * 0.2f;
            db.x = fmaf(p4.x, piv, db.x); db.y = fmaf(p4.y, piv, db.y);
            db.z = fmaf(p4.z, piv, db.z); db.w = fmaf(p4.w, piv, db.w);
        }
        reinterpret_cast<float4*>(&sm.dbar[e][0])[lane] = db;
    }

    // ---------------- LN: warp t (full-warp reduction, no staging) ----------
    {
        const int t = warp;
        const long g = g0 + t;
        const float4* xr = reinterpret_cast<const float4*>(x + g * DD);
        float4 v[8];
        float s = 0.0f, sq = 0.0f;
        #pragma unroll
        for (int i = 0; i < 8; i++) {
            v[i] = xr[i * 32 + lane];
            s  += v[i].x + v[i].y + v[i].z + v[i].w;
            sq += v[i].x * v[i].x + v[i].y * v[i].y + v[i].z * v[i].z + v[i].w * v[i].w;
        }
        #pragma unroll
        for (int o = 16; o; o >>= 1) {
            s  += __shfl_xor_sync(0xffffffffu, s,  o);
            sq += __shfl_xor_sync(0xffffffffu, sq, o);
        }
        float mean = s * (1.0f / DD);
        float rstd = rsqrtf(sq * (1.0f / DD) - mean * mean + 1e-5f);
        #pragma unroll
        for (int i = 0; i < 8; i++) {
            int c4 = i * 32 + lane;
            float4 gm = reinterpret_cast<const float4*>(ln_gamma)[c4];
            float4 bt = reinterpret_cast<const float4*>(ln_beta)[c4];
            int c = c4 * 4;
            sm.fT[c + 0][t] = (v[i].x - mean) * rstd * gm.x + bt.x;
            sm.fT[c + 1][t] = (v[i].y - mean) * rstd * gm.y + bt.y;
            sm.fT[c + 2][t] = (v[i].z - mean) * rstd * gm.z + bt.z;
            sm.fT[c + 3][t] = (v[i].w - mean) * rstd * gm.w + bt.w;
        }
    }
    __syncthreads();   // S1: fT(xn), we_s/aw_s/dbar ready

    // ---------------- P1 (tid 256..511): masks / mw --------------------------
    if (tid >= 256) {
        const int q = tid - 256;
        const int t = q >> 4, e = q & 15;
        const long g = g0 + t;
        float f = fingerprints[(int)(g & (PP - 1))];
        float fmin = fmaxf(0.0f, e * (1.0f / EE) - 0.03125f);
        float fmax = fminf(1.0f, (e + 1) * (1.0f / EE) + 0.03125f);
        float mval = (f >= fmin && f < fmax) ? 1.0f : 0.0f;
        sm.mask_s[t][e] = mval;
        sm.mw_s[t][e]   = mval * sm.we_s[e];
    }
    // ---------------- P3 (tid 0..255): gate hidden (FFMA2 over token pairs) --
    if (tid < EE * HH) {
        const int e = tid >> 4, j = tid & 15;
        ull acc[8];
        #pragma unroll
        for (int p = 0; p < 8; p++) acc[p] = 0ull;
        const float* w1p = w1 + (long)(e * SS) * HH + j;
        #pragma unroll 4
        for (int s = 0; s < SS; s++) {
            float w = w1p[s * HH];
            ull wd = pk(w, w);
            const ull* fp = reinterpret_cast<const ull*>(&sm.fT[e * SS + s][0]);
            #pragma unroll
            for (int p = 0; p < 8; p++) ffma2(acc[p], fp[p], wd);
        }
        float b1v = b1[e * HH + j];
        ull* hrow = reinterpret_cast<ull*>(&h_s[e][j][0]);
        #pragma unroll
        for (int p = 0; p < 8; p++) {
            float h0, h1; upk(acc[p], h0, h1);
            h0 += b1v; h1 += b1v;
            h0 = 0.5f * h0 * (1.0f + erff(h0 * 0.70710678118654752f));
            h1 = 0.5f * h1 * (1.0f + erff(h1 * 0.70710678118654752f));
            hrow[p] = pk(h0, h1);
        }
    }
    __syncthreads();   // S2: h, mw ready

    // ---------------- P4: gate out + gscale ; den ----------------------------
    if (tid < TOK * EE) {
        const int t = tid >> 4, e = tid & 15;
        float s = 0.0f;
        #pragma unroll
        for (int j = 0; j < HH; j++) s += h_s[e][j][t] * w2[e * HH + j];
        float gate = sigmoidf_(s + b2[e]);
        float aw = sm.aw_s[e];
        sm.gscale[e][t] = gate * aw + (1.0f - aw);
    } else if (tid < TOK * EE + TOK) {
        const int t = tid - TOK * EE;
        float s = 0.0f;
        #pragma unroll
        for (int e = 0; e < EE; e++) s += sm.mw_s[t][e];
        sm.den_s[t] = fmaxf(s, 1e-6f);
    }
    __syncthreads();   // S3

    // ---------------- P5: f = xn * gscale (packed mul) -----------------------
    {
        const int c0 = tid * 2;
        #pragma unroll
        for (int cc = 0; cc < 2; cc++) {
            const int c = c0 + cc;
            const int e = c >> 6;
            ull* fp = reinterpret_cast<ull*>(&sm.fT[c][0]);
            const ull* gp = reinterpret_cast<const ull*>(&sm.gscale[e][0]);
            #pragma unroll
            for (int k = 0; k < 8; k++) fp[k] = mul2(fp[k], gp[k]);
        }
    }
    __syncthreads();   // S4

    // ---------------- P6: V[e] = f_e @ wv[e]  (warp e, 16 tok x 4 d / thread)
    {
        const int e = warp;
        ull acc[8][4];
        #pragma unroll
        for (int p = 0; p < 8; p++)
            #pragma unroll
            for (int d = 0; d < 4; d++) acc[p][d] = 0ull;
        const float4* wvp = reinterpret_cast<const float4*>(wv + (long)e * SS * DKK) + lane;
        const ull* fbase = reinterpret_cast<const ull*>(&sm.fT[e * SS][0]);
        #pragma unroll 2
        for (int s = 0; s < SS; s++) {
            float4 w4 = wvp[s * 32];
            ull wd0 = pk(w4.x, w4.x), wd1 = pk(w4.y, w4.y);
            ull wd2 = pk(w4.z, w4.z), wd3 = pk(w4.w, w4.w);
            const ull* fp = fbase + s * (TOKP / 2);
            #pragma unroll
            for (int p = 0; p < 8; p++) {
                ull f = fp[p];
                ffma2(acc[p][0], f, wd0);
                ffma2(acc[p][1], f, wd1);
                ffma2(acc[p][2], f, wd2);
                ffma2(acc[p][3], f, wd3);
            }
        }
        #pragma unroll
        for (int p = 0; p < 8; p++) {
            float4 lo, hi;
            upk(acc[p][0], lo.x, hi.x); upk(acc[p][1], lo.y, hi.y);
            upk(acc[p][2], lo.z, hi.z); upk(acc[p][3], lo.w, hi.w);
            *reinterpret_cast<float4*>(&sm.V2[e][2 * p + 0][lane * 4]) = lo;
            *reinterpret_cast<float4*>(&sm.V2[e][2 * p + 1][lane * 4]) = hi;
        }
    }
    __syncthreads();   // S5

    // ---------------- P7: Vdb[t][e] = V[e][t] . dbar[e]  (warp e) ------------
    {
        const int e = warp;
        ulonglong2 dbv = reinterpret_cast<const ulonglong2*>(&sm.dbar[e][0])[lane];
        #pragma unroll
        for (int t = 0; t < TOK; t++) {
            ulonglong2 vv = reinterpret_cast<const ulonglong2*>(&sm.V2[e][t][0])[lane];
            ull a = 0ull;
            ffma2(a, vv.x, dbv.x);
            ffma2(a, vv.y, dbv.y);
            float lo, hi; upk(a, lo, hi);
            float d = lo + hi;
            #pragma unroll
            for (int o = 16; o; o >>= 1) d += __shfl_xor_sync(0xffffffffu, d, o);
            if (lane == 0) sm.Vdb[t][e] = d;
        }
    }
    __syncthreads();   // S6

    // ---------------- P8: fused scalar ---------------------------------------
    if (tid < TOK) {
        const int t = tid;
        float s = 0.0f;
        #pragma unroll
        for (int e = 0; e < EE; e++) s += sm.mw_s[t][e] * sm.Vdb[t][e];
        sm.fused_s[t] = s / (sm.den_s[t] * fabsf(temperature[0]));
    }
    __syncthreads();   // S7

    // ---------------- P9: rec = (V*fused) @ wout, mask, residual -------------
    {
        const int e  = tid >> 5;            // warp == expert
        const int th = (tid >> 4) & 1;      // token-octet
        const int sl = tid & 15;            // s quad
        ull acc[8][2];
        #pragma unroll
        for (int ti = 0; ti < 8; ti++) { acc[ti][0] = 0ull; acc[ti][1] = 0ull; }
        const float* wob = wout + (long)e * DKK * SS + sl * 4;
        #pragma unroll 2
        for (int db = 0; db < DKK / 4; db++) {
            float vtf[8][4];
            #pragma unroll
            for (int ti = 0; ti < 8; ti++) {
                float4 vt = *reinterpret_cast<const float4*>(&sm.V2[e][th * 8 + ti][db * 4]);
                vtf[ti][0] = vt.x; vtf[ti][1] = vt.y; vtf[ti][2] = vt.z; vtf[ti][3] = vt.w;
            }
            #pragma unroll
            for (int i = 0; i < 4; i++) {
                ulonglong2 wp = *reinterpret_cast<const ulonglong2*>(wob + (db * 4 + i) * SS);
                #pragma unroll
                for (int ti = 0; ti < 8; ti++) {
                    ull a = pk(vtf[ti][i], vtf[ti][i]);
                    ffma2(acc[ti][0], a, wp.x);
                    ffma2(acc[ti][1], a, wp.y);
                }
            }
        }
        #pragma unroll
        for (int ti = 0; ti < 8; ti++) {
            const int t = th * 8 + ti;
            const long g = g0 + t;
            float fs = sm.fused_s[t] * sm.mask_s[t][e];
            float a0, a1, a2, a3;
            upk(acc[ti][0], a0, a1);
            upk(acc[ti][1], a2, a3);
            const float4 xv = *reinterpret_cast<const float4*>(x + g * DD + e * SS + sl * 4);
            float4 ov;
            ov.x = xv.x + fs * a0;
            ov.y = xv.y + fs * a1;
            ov.z = xv.z + fs * a2;
            ov.w = xv.w + fs * a3;
            *reinterpret_cast<float4*>(out + g * DD + e * SS + sl * 4) = ov;
        }
    }
}

extern "C" void kernel_launch(void* const* d_in, const int* in_sizes, int n_in,
                              void* d_out, int out_size)
{
    (void)in_sizes; (void)n_in; (void)out_size;
    const float* x            = (const float*)d_in[0];
    const float* fingerprints = (const float*)d_in[1];
    const float* ln_gamma     = (const float*)d_in[2];
    const float* ln_beta      = (const float*)d_in[3];
    const float* w1           = (const float*)d_in[4];
    const float* b1           = (const float*)d_in[5];
    const float* w2           = (const float*)d_in[6];
    const float* b2           = (const float*)d_in[7];
    const float* alpha        = (const float*)d_in[8];
    const float* wv           = (const float*)d_in[9];
    const float* penta        = (const float*)d_in[10];
    const float* betas        = (const float*)d_in[11];
    const float* wout         = (const float*)d_in[12];
    const float* pos_embed    = (const float*)d_in[13];
    const float* temperature  = (const float*)d_in[14];
    float* out = (float*)d_out;

    cudaFuncSetAttribute(cantor_moe_kernel,
                         cudaFuncAttributeMaxDynamicSharedMemorySize,
                         (int)sizeof(Smem));

    dim3 grid(NTOK / TOK);
    cantor_moe_kernel<<<grid, THREADS, sizeof(Smem)>>>(
        x, fingerprints, ln_gamma, ln_beta, w1, b1, w2, b2, alpha,
        wv, penta, betas, wout, pos_embed, temperature, out);
}

// round 7
// speedup vs baseline: 2.6308x; 1.8196x over previous
#include <cuda_runtime.h>
#include <math.h>

// Problem constants
#define BB   8
#define PP   2048
#define DD   1024
#define EE   16
#define SS   64
#define DKK  128
#define HH   16
#define NTOK (BB*PP)          // 16384
#define TOK  16               // tokens per CTA
#define TOKP 18               // padded token row (bank-conflict-free for stride-18 tricks)
#define THREADS 512

typedef unsigned long long ull;

__device__ __forceinline__ float sigmoidf_(float v) { return 1.0f / (1.0f + expf(-v)); }

// packed f32x2 helpers (sm_100+)
__device__ __forceinline__ ull pk(float lo, float hi) {
    ull r; asm("mov.b64 %0,{%1,%2};" : "=l"(r) : "f"(lo), "f"(hi)); return r;
}
__device__ __forceinline__ void upk(ull v, float& lo, float& hi) {
    asm("mov.b64 {%0,%1},%2;" : "=f"(lo), "=f"(hi) : "l"(v));
}
__device__ __forceinline__ void ffma2(ull& acc, ull a, ull b) {
    asm("fma.rn.f32x2 %0,%1,%2,%0;" : "+l"(acc) : "l"(a), "l"(b));
}
__device__ __forceinline__ ull add2(ull a, ull b) {
    ull r; asm("add.rn.f32x2 %0,%1,%2;" : "=l"(r) : "l"(a), "l"(b)); return r;
}

// ---- precomputed per-expert constants (device globals: no allocation) ------
__device__ float gC[EE][SS][SS];   // C_e = wv_e @ wout_e   (64x64)
__device__ float gQ[EE][SS];       // q_e = wv_e @ dbar_e   (64)
__device__ float gWE[EE];          // pos_w * beta_w
__device__ float gAW[EE];          // sigmoid(alpha)

// ============================ pre-kernel ====================================
// grid = 64: blockIdx.x = e*4 + quad ; 256 threads
__global__ void precomp_kernel(
    const float* __restrict__ wv,
    const float* __restrict__ wout,
    const float* __restrict__ penta,
    const float* __restrict__ betas,
    const float* __restrict__ alpha,
    const float* __restrict__ pos_embed)
{
    const int e = blockIdx.x >> 2;
    const int q = blockIdx.x & 3;
    const int tid = threadIdx.x;
    const int warp = tid >> 5, lane = tid & 31;

    __shared__ float pinv[5];
    __shared__ float dbar[DKK];

    if (q == 0) {
        // inverse norms of penta rows (warps 0..4)
        if (warp < 5) {
            float4 p = reinterpret_cast<const float4*>(penta + (long)(e * 5 + warp) * DKK)[lane];
            float sq = p.x * p.x + p.y * p.y + p.z * p.z + p.w * p.w;
            #pragma unroll
            for (int o = 16; o; o >>= 1) sq += __shfl_xor_sync(0xffffffffu, sq, o);
            if (lane == 0) pinv[warp] = rsqrtf(sq) * 0.2f;
        }
        // scalars (warp 6)
        if (warp == 6) {
            float4 pv = reinterpret_cast<const float4*>(pos_embed)[e * 32 + lane];
            float s = pv.x + pv.y + pv.z + pv.w;
            #pragma unroll
            for (int o = 16; o; o >>= 1) s += __shfl_xor_sync(0xffffffffu, s, o);
            if (lane == 0) {
                float pos_w = sigmoidf_(s * (1.0f / 128.0f));
                const int offs[4] = {-2, -1, 1, 2};
                float nv = 0.0f, bs = 0.0f;
                #pragma unroll
                for (int j = 0; j < 4; j++) {
                    int nb = e + offs[j];
                    if (nb >= 0 && nb < EE) { nv += 1.0f; bs += sigmoidf_(betas[e * 4 + j]); }
                }
                gWE[e] = pos_w * (1.0f + bs / nv);
                gAW[e] = sigmoidf_(alpha[e]);
            }
        }
        __syncthreads();
        if (tid < DKK) {
            float a = 0.0f;
            #pragma unroll
            for (int v = 0; v < 5; v++)
                a = fmaf(penta[(long)(e * 5 + v) * DKK + tid], pinv[v], a);
            dbar[tid] = a;
        }
        __syncthreads();
        if (tid < SS) {
            const float* wvp = wv + ((long)e * SS + tid) * DKK;
            float a = 0.0f;
            for (int d = 0; d < DKK; d++) a = fmaf(wvp[d], dbar[d], a);
            gQ[e][tid] = a;
        }
    }

    // C_e rows [q*16, q*16+16): thread -> (s, 4 cols)
    {
        const int s  = q * 16 + (tid >> 4);
        const int c0 = (tid & 15) * 4;
        float4 acc = make_float4(0.f, 0.f, 0.f, 0.f);
        const float* wvp = wv + ((long)e * SS + s) * DKK;
        const float* wop = wout + (long)e * DKK * SS + c0;
        #pragma unroll 4
        for (int d = 0; d < DKK; d++) {
            float a = wvp[d];
            float4 w = *reinterpret_cast<const float4*>(wop + (long)d * SS);
            acc.x = fmaf(a, w.x, acc.x); acc.y = fmaf(a, w.y, acc.y);
            acc.z = fmaf(a, w.z, acc.z); acc.w = fmaf(a, w.w, acc.w);
        }
        *reinterpret_cast<float4*>(&gC[e][s][c0]) = acc;
    }
}

// ============================ main kernel ===================================
struct __align__(16) Smem {
    float fT[DD][TOKP];         // 73728 B : xn, [channel][token], token pairs 8B-contig
    float h_s[EE][HH][TOKP];    // 18432 B : gate hidden (pad 18 -> conflict-free ull stores)
    float Vdbraw[TOK][EE];      // xn_e . q_e  (pre-gscale)
    float gscale[EE][TOK];
    float mask_s[TOK][EE];
    float mw_s[TOK][EE];
    float den_s[TOK];
    float fused_s[TOK];
};

__global__ __launch_bounds__(THREADS, 2)
void cantor_moe_kernel(
    const float* __restrict__ x,
    const float* __restrict__ fingerprints,
    const float* __restrict__ ln_gamma,
    const float* __restrict__ ln_beta,
    const float* __restrict__ w1,
    const float* __restrict__ b1,
    const float* __restrict__ w2,
    const float* __restrict__ b2,
    const float* __restrict__ temperature,
    float* __restrict__ out)
{
    extern __shared__ unsigned char smem_raw[];
    Smem& sm = *reinterpret_cast<Smem*>(smem_raw);

    const int tid  = threadIdx.x;
    const int warp = tid >> 5;
    const int lane = tid & 31;
    const long g0  = (long)blockIdx.x * TOK;

    // ---------------- LN: warp t, two-pass (low register pressure) ----------
    {
        const int t = warp;
        const long g = g0 + t;
        const float4* xr = reinterpret_cast<const float4*>(x + g * DD);
        float s = 0.0f, sq = 0.0f;
        #pragma unroll
        for (int i = 0; i < 8; i++) {
            float4 v = xr[i * 32 + lane];
            s  += v.x + v.y + v.z + v.w;
            sq += v.x * v.x + v.y * v.y + v.z * v.z + v.w * v.w;
        }
        #pragma unroll
        for (int o = 16; o; o >>= 1) {
            s  += __shfl_xor_sync(0xffffffffu, s,  o);
            sq += __shfl_xor_sync(0xffffffffu, sq, o);
        }
        float mean = s * (1.0f / DD);
        float rstd = rsqrtf(sq * (1.0f / DD) - mean * mean + 1e-5f);
        #pragma unroll
        for (int i = 0; i < 8; i++) {
            int c4 = i * 32 + lane;
            float4 v  = xr[c4];                      // L1 hit (second pass)
            float4 gm = reinterpret_cast<const float4*>(ln_gamma)[c4];
            float4 bt = reinterpret_cast<const float4*>(ln_beta)[c4];
            int c = c4 * 4;
            sm.fT[c + 0][t] = (v.x - mean) * rstd * gm.x + bt.x;
            sm.fT[c + 1][t] = (v.y - mean) * rstd * gm.y + bt.y;
            sm.fT[c + 2][t] = (v.z - mean) * rstd * gm.z + bt.z;
            sm.fT[c + 3][t] = (v.w - mean) * rstd * gm.w + bt.w;
        }
    }
    __syncthreads();   // S1: fT(xn) ready

    // -------- Phase B: tid<256 gate hidden | tid>=256 masks + Vdbraw --------
    if (tid < EE * HH) {
        const int e = tid >> 4, j = tid & 15;
        ull acc[8];
        #pragma unroll
        for (int p = 0; p < 8; p++) acc[p] = 0ull;
        const float* w1p = w1 + (long)(e * SS) * HH + j;
        #pragma unroll 4
        for (int s = 0; s < SS; s++) {
            float w = w1p[s * HH];
            ull wd = pk(w, w);
            const ull* fp = reinterpret_cast<const ull*>(&sm.fT[e * SS + s][0]);
            #pragma unroll
            for (int p = 0; p < 8; p++) ffma2(acc[p], fp[p], wd);
        }
        float b1v = b1[e * HH + j];
        ull* hrow = reinterpret_cast<ull*>(&sm.h_s[e][j][0]);
        #pragma unroll
        for (int p = 0; p < 8; p++) {
            float h0, h1; upk(acc[p], h0, h1);
            h0 += b1v; h1 += b1v;
            h0 = 0.5f * h0 * (1.0f + erff(h0 * 0.70710678118654752f));
            h1 = 0.5f * h1 * (1.0f + erff(h1 * 0.70710678118654752f));
            hrow[p] = pk(h0, h1);
        }
    } else {
        // masks / mw
        {
            const int qq = tid - 256;
            const int t = qq >> 4, e = qq & 15;
            const long g = g0 + t;
            float f = fingerprints[(int)(g & (PP - 1))];
            float fmin = fmaxf(0.0f, e * (1.0f / EE) - 0.03125f);
            float fmax = fminf(1.0f, (e + 1) * (1.0f / EE) + 0.03125f);
            float mval = (f >= fmin && f < fmax) ? 1.0f : 0.0f;
            sm.mask_s[t][e] = mval;
            sm.mw_s[t][e]   = mval * gWE[e];
        }
        // Vdbraw: warp w (8..15) handles experts w-8 and w
        #pragma unroll
        for (int ee = 0; ee < 2; ee++) {
            const int e = (warp - 8) + ee * 8;
            ull acc[8];
            #pragma unroll
            for (int p = 0; p < 8; p++) acc[p] = 0ull;
            #pragma unroll
            for (int si = 0; si < 2; si++) {
                const int s = lane + si * 32;
                float qv = gQ[e][s];
                ull qd = pk(qv, qv);
                const ull* fp = reinterpret_cast<const ull*>(&sm.fT[e * SS + s][0]);
                #pragma unroll
                for (int p = 0; p < 8; p++) ffma2(acc[p], fp[p], qd);
            }
            #pragma unroll
            for (int o = 16; o; o >>= 1)
                #pragma unroll
                for (int p = 0; p < 8; p++)
                    acc[p] = add2(acc[p], __shfl_xor_sync(0xffffffffu, acc[p], o));
            if (lane == 0) {
                #pragma unroll
                for (int p = 0; p < 8; p++) {
                    float lo, hi; upk(acc[p], lo, hi);
                    sm.Vdbraw[2 * p + 0][e] = lo;
                    sm.Vdbraw[2 * p + 1][e] = hi;
                }
            }
        }
    }
    __syncthreads();   // S2: h, mask, mw, Vdbraw ready

    // -------- Phase C: gscale (tid<256, e-major) + den ----------------------
    if (tid < TOK * EE) {
        const int e = tid >> 4, t = tid & 15;
        float s = 0.0f;
        #pragma unroll
        for (int j = 0; j < HH; j++) s += sm.h_s[e][j][t] * w2[e * HH + j];
        float gate = sigmoidf_(s + b2[e]);
        float aw = gAW[e];
        sm.gscale[e][t] = gate * aw + (1.0f - aw);
    } else if (tid < TOK * EE + TOK) {
        const int t = tid - TOK * EE;
        float s = 0.0f;
        #pragma unroll
        for (int e = 0; e < EE; e++) s += sm.mw_s[t][e];
        sm.den_s[t] = fmaxf(s, 1e-6f);
    }
    __syncthreads();   // S3

    // -------- Phase D: fused scalar (gscale folded in) ----------------------
    if (tid < TOK) {
        const int t = tid;
        float s = 0.0f;
        #pragma unroll
        for (int e = 0; e < EE; e++)
            s += sm.mw_s[t][e] * sm.gscale[e][t] * sm.Vdbraw[t][e];
        sm.fused_s[t] = s / (sm.den_s[t] * fabsf(temperature[0]));
    }
    __syncthreads();   // S4

    // -------- Phase E: out = x + cscale * (xn_e @ C_e)  (warp e) ------------
    {
        const int e = warp;
        ull acc[8][2];                       // [token-pair][col 2lane / 2lane+1]
        #pragma unroll
        for (int p = 0; p < 8; p++) { acc[p][0] = 0ull; acc[p][1] = 0ull; }
        const float* Cb = &gC[e][0][2 * lane];
        const ull* fbase = reinterpret_cast<const ull*>(&sm.fT[e * SS][0]);
        #pragma unroll 2
        for (int s = 0; s < SS; s++) {
            float2 cw = *reinterpret_cast<const float2*>(Cb + (long)s * SS);
            ull c0 = pk(cw.x, cw.x), c1 = pk(cw.y, cw.y);
            const ull* fp = fbase + s * (TOKP / 2);
            #pragma unroll
            for (int p = 0; p < 8; p++) {
                ull f = fp[p];
                ffma2(acc[p][0], f, c0);
                ffma2(acc[p][1], f, c1);
            }
        }
        const float* xb = x + g0 * DD + e * SS + 2 * lane;
        float* ob = out + g0 * DD + e * SS + 2 * lane;
        #pragma unroll
        for (int p = 0; p < 8; p++) {
            float a0lo, a0hi, a1lo, a1hi;
            upk(acc[p][0], a0lo, a0hi);
            upk(acc[p][1], a1lo, a1hi);
            const int t0 = 2 * p, t1 = 2 * p + 1;
            float cs0 = sm.fused_s[t0] * sm.mask_s[t0][e] * sm.gscale[e][t0];
            float cs1 = sm.fused_s[t1] * sm.mask_s[t1][e] * sm.gscale[e][t1];
            float2 xv0 = *reinterpret_cast<const float2*>(xb + (long)t0 * DD);
            float2 xv1 = *reinterpret_cast<const float2*>(xb + (long)t1 * DD);
            float2 o0, o1;
            o0.x = xv0.x + cs0 * a0lo; o0.y = xv0.y + cs0 * a1lo;
            o1.x = xv1.x + cs1 * a0hi; o1.y = xv1.y + cs1 * a1hi;
            *reinterpret_cast<float2*>(ob + (long)t0 * DD) = o0;
            *reinterpret_cast<float2*>(ob + (long)t1 * DD) = o1;
        }
    }
}

extern "C" void kernel_launch(void* const* d_in, const int* in_sizes, int n_in,
                              void* d_out, int out_size)
{
    (void)in_sizes; (void)n_in; (void)out_size;
    const float* x            = (const float*)d_in[0];
    const float* fingerprints = (const float*)d_in[1];
    const float* ln_gamma     = (const float*)d_in[2];
    const float* ln_beta      = (const float*)d_in[3];
    const float* w1           = (const float*)d_in[4];
    const float* b1           = (const float*)d_in[5];
    const float* w2           = (const float*)d_in[6];
    const float* b2           = (const float*)d_in[7];
    const float* alpha        = (const float*)d_in[8];
    const float* wv           = (const float*)d_in[9];
    const float* penta        = (const float*)d_in[10];
    const float* betas        = (const float*)d_in[11];
    const float* wout         = (const float*)d_in[12];
    const float* pos_embed    = (const float*)d_in[13];
    const float* temperature  = (const float*)d_in[14];
    float* out = (float*)d_out;

    precomp_kernel<<<64, 256>>>(wv, wout, penta, betas, alpha, pos_embed);

    cudaFuncSetAttribute(cantor_moe_kernel,
                         cudaFuncAttributeMaxDynamicSharedMemorySize,
                         (int)sizeof(Smem));

    dim3 grid(NTOK / TOK);
    cantor_moe_kernel<<<grid, THREADS, sizeof(Smem)>>>(
        x, fingerprints, ln_gamma, ln_beta, w1, b1, w2, b2,
        temperature, out);
}